// round 5
// baseline (speedup 1.0000x reference)
#include <cuda_runtime.h>

// (B, N, T, H) = (16, 256, 96, 128)
#define BB 16
#define NN 256
#define TT 96
#define HH 128
#define EPS 1e-5f
#define G  4            // (b,n) pairs per block in the main kernel

// Scratch (static __device__ — allocation-free)
__device__ float g_C[TT * HH];       // time_emb @ W3            (48 KB)
__device__ float g_nodeS[NN * HH];   // node_emb @ W2            (128 KB)
__device__ float g_Wf[TT * HH];      // Wp @ W1  (fused proj)    (48 KB)
__device__ float g_bias[HH];         // bp @ W1 + bf

// 16-lane-group f32 sum: 4-round shfl butterfly (offsets 1..8 stay inside
// each 16-lane half). redux.sync.add.f32 is NOT available on sm_103a.
__device__ __forceinline__ float group16_sum(float v) {
#pragma unroll
    for (int off = 1; off < 16; off <<= 1)
        v += __shfl_xor_sync(0xffffffffu, v, off);
    return v;
}

// ---------------------------------------------------------------------------
// Prep kernel: all the tiny GEMMs. 449 blocks x 512 threads, 4-way split-K.
//   r in [0,96)    : g_C[t=r]       = time_emb[r]   @ W3
//   r in [96,192)  : g_Wf[t=r-96]   = Wp[r-96]      @ W1
//   r in [192,448) : g_nodeS[r-192] = node_emb[..]  @ W2
//   r == 448       : g_bias         = bp @ W1 + bf
// ---------------------------------------------------------------------------
__global__ __launch_bounds__(512) void prep_kernel(
    const float* __restrict__ Wp,
    const float* __restrict__ bp,
    const float* __restrict__ Wf,
    const float* __restrict__ bf,
    const float* __restrict__ node_emb,
    const float* __restrict__ time_emb) {

    __shared__ float vsh[HH];
    __shared__ float partial[4][HH];

    const int r = blockIdx.x;
    const int k = threadIdx.x & (HH - 1);
    const int p = threadIdx.x >> 7;       // 0..3

    const float* __restrict__ v;
    const float* __restrict__ W;
    if (r < TT)                { v = time_emb + r * HH;        W = Wf + 2 * HH * HH; }
    else if (r < 2 * TT)       { v = Wp + (r - TT) * HH;       W = Wf; }
    else if (r < 2 * TT + NN)  { v = node_emb + (r - 2*TT)*HH; W = Wf + HH * HH; }
    else                       { v = bp;                       W = Wf; }

    if (threadIdx.x < HH) vsh[threadIdx.x] = v[threadIdx.x];
    __syncthreads();

    float acc = 0.f;
    const int h0 = p * 32;
#pragma unroll
    for (int hh = 0; hh < 32; hh++) {
        const int h = h0 + hh;
        acc += vsh[h] * W[h * HH + k];   // coalesced over k
    }
    partial[p][k] = acc;
    __syncthreads();

    if (threadIdx.x < HH) {
        float s = partial[0][k] + partial[1][k] + partial[2][k] + partial[3][k];
        if (r < TT)               g_C[r * HH + k] = s;
        else if (r < 2 * TT)      g_Wf[(r - TT) * HH + k] = s;
        else if (r < 2 * TT + NN) g_nodeS[(r - 2 * TT) * HH + k] = s;
        else                      g_bias[k] = s + bf[k];
    }
}

// ---------------------------------------------------------------------------
// Main kernel: 1024 blocks x 256 threads; block handles G=4 (b,n) pairs.
// Phase 1: As[g,k] = bias[k] + nodeS[n,k] + sum_t xs[g,t] * Wfused[t,k]
// Phase 2: 16 lanes per row, 2 rows per warp per pass (rgrp = lane>>4).
//   Lane il=lane&15 owns cols {4il..4il+4} and {64+4il..+4}: each STG.128
//   across the warp writes two contiguous 256B row segments.
//   Registers hold gamma/beta (once) and A (once per pair); C streams via
//   __ldg (48KB, L1-resident). Row mean/var via 4-round shfl butterfly.
// ---------------------------------------------------------------------------
__global__ __launch_bounds__(256, 4) void gpe_main_kernel(
    const float* __restrict__ x,
    const float* __restrict__ gamma,
    const float* __restrict__ beta,
    float* __restrict__ out) {

    __shared__ float xs[G * TT];
    __shared__ float As[G * HH];

    const int tid   = threadIdx.x;
    const int pair0 = blockIdx.x * G;

    for (int i = tid; i < G * TT; i += 256)
        xs[i] = x[(size_t)pair0 * TT + i];
    __syncthreads();

    // Phase 1: 512 outputs, 2 per thread, 96 FMA each
    for (int i = tid; i < G * HH; i += 256) {
        const int g = i >> 7;
        const int k = i & (HH - 1);
        const int n = (pair0 + g) & (NN - 1);
        float acc = __ldg(g_bias + k) + __ldg(g_nodeS + n * HH + k);
        const float* __restrict__ xg = xs + g * TT;
#pragma unroll 8
        for (int t = 0; t < TT; t++)
            acc += xg[t] * g_Wf[t * HH + k];
        As[i] = acc;
    }
    __syncthreads();

    // Phase 2
    const int w    = tid >> 5;
    const int l    = tid & 31;
    const int rgrp = l >> 4;          // which of the 2 rows this pass
    const int il   = l & 15;
    const int col0 = 4 * il;          // second chunk at col0 + 64

    // gamma/beta resident in registers for the whole kernel
    const float4 g0 = __ldg(reinterpret_cast<const float4*>(gamma + col0));
    const float4 g1 = __ldg(reinterpret_cast<const float4*>(gamma + 64 + col0));
    const float4 b0 = __ldg(reinterpret_cast<const float4*>(beta + col0));
    const float4 b1 = __ldg(reinterpret_cast<const float4*>(beta + 64 + col0));

    for (int g = 0; g < G; g++) {
        // A slice for this pair, resident in registers across all 96 rows
        const float4 a0 = *reinterpret_cast<const float4*>(As + g * HH + col0);
        const float4 a1 = *reinterpret_cast<const float4*>(As + g * HH + 64 + col0);
        float* __restrict__ obase = out + ((size_t)(pair0 + g) * TT) * HH;

#pragma unroll 2
        for (int pass = 0; pass < 6; pass++) {
            const int row = pass * 16 + w * 2 + rgrp;
            const float* __restrict__ crow = g_C + row * HH;
            const float4 c0 = __ldg(reinterpret_cast<const float4*>(crow + col0));
            const float4 c1 = __ldg(reinterpret_cast<const float4*>(crow + 64 + col0));

            float4 v0, v1;
            v0.x = fmaxf(a0.x + c0.x, 0.f);
            v0.y = fmaxf(a0.y + c0.y, 0.f);
            v0.z = fmaxf(a0.z + c0.z, 0.f);
            v0.w = fmaxf(a0.w + c0.w, 0.f);
            v1.x = fmaxf(a1.x + c1.x, 0.f);
            v1.y = fmaxf(a1.y + c1.y, 0.f);
            v1.z = fmaxf(a1.z + c1.z, 0.f);
            v1.w = fmaxf(a1.w + c1.w, 0.f);

            float s1 = v0.x + v0.y + v0.z + v0.w
                     + v1.x + v1.y + v1.z + v1.w;
            float s2 = v0.x * v0.x + v0.y * v0.y + v0.z * v0.z + v0.w * v0.w
                     + v1.x * v1.x + v1.y * v1.y + v1.z * v1.z + v1.w * v1.w;

            s1 = group16_sum(s1);
            s2 = group16_sum(s2);

            const float mean = s1 * (1.f / HH);
            const float var  = s2 * (1.f / HH) - mean * mean;
            const float rstd = rsqrtf(var + EPS);

            float4 o0, o1;
            o0.x = (v0.x - mean) * rstd * g0.x + b0.x;
            o0.y = (v0.y - mean) * rstd * g0.y + b0.y;
            o0.z = (v0.z - mean) * rstd * g0.z + b0.z;
            o0.w = (v0.w - mean) * rstd * g0.w + b0.w;
            o1.x = (v1.x - mean) * rstd * g1.x + b1.x;
            o1.y = (v1.y - mean) * rstd * g1.y + b1.y;
            o1.z = (v1.z - mean) * rstd * g1.z + b1.z;
            o1.w = (v1.w - mean) * rstd * g1.w + b1.w;

            float* __restrict__ orow = obase + row * HH;
            __stcs(reinterpret_cast<float4*>(orow + col0), o0);
            __stcs(reinterpret_cast<float4*>(orow + 64 + col0), o1);
        }
    }
}

// ---------------------------------------------------------------------------
// Inputs: 0:x 1:Wp 2:bp 3:Wf 4:bf 5:gamma 6:beta 7:node_emb 8:time_emb
// ---------------------------------------------------------------------------
extern "C" void kernel_launch(void* const* d_in, const int* in_sizes, int n_in,
                              void* d_out, int out_size) {
    const float* x        = (const float*)d_in[0];
    const float* Wp       = (const float*)d_in[1];
    const float* bp       = (const float*)d_in[2];
    const float* Wf       = (const float*)d_in[3];
    const float* bf       = (const float*)d_in[4];
    const float* gamma    = (const float*)d_in[5];
    const float* beta     = (const float*)d_in[6];
    const float* node_emb = (const float*)d_in[7];
    const float* time_emb = (const float*)d_in[8];
    float* out = (float*)d_out;

    prep_kernel<<<2 * TT + NN + 1, 512>>>(Wp, bp, Wf, bf, node_emb, time_emb);
    gpe_main_kernel<<<(BB * NN) / G, 256>>>(x, gamma, beta, out);
}